// round 5
// baseline (speedup 1.0000x reference)
#include <cuda_runtime.h>
#include <math.h>

#define H 512
#define HEADS 8
#define DK 64
#define NCLASS 4
#define VOCAB 5000
#define LW 32
#define NLEAF 20000
#define NPAR 20000
#define NTOT (NLEAF + NPAR)
#define DEG 4
#define NLAYER 5
#define MAXB 64
#define MAXL 512
#define MAXT 1024
#define SUBT 48
#define MAXTASK (NPAR + SUBT * MAXT)

// ---- static device scratch ----
__device__ float g_Et[VOCAB * H];
__device__ float g_xe[NTOT * H];
__device__ float g_gz[NPAR * H];   // Wz@xe+bz  (+= Uz@mem) -> z
__device__ float g_gr[NPAR * H];   // Wr@xe+br  (+= Ur@mem) -> mem*r
__device__ float g_gh[NPAR * H];   // Wh@xe+bh  (+= Uh@(mem*r))
__device__ float g_mem[NPAR * H];
__device__ float g_ph[NPAR * H];
__device__ float g_pmax[MAXB * H];

__device__ int g_lvl[NPAR];
__device__ int g_lstart[MAXL + 2];
__device__ int g_nlev;
__device__ int g_order[NPAR];

// task queue + dependency counters
__device__ int g_ptile[NPAR];
__device__ int g_tile_start[MAXT];
__device__ int g_tile_cnt[MAXT];
__device__ int g_mem_cnt[MAXT];     // A completions (target mtile)
__device__ int g_zrj[MAXT * 8];     // per (tile, zr j-chunk) k-part count (target 4)
__device__ int g_zdone[MAXT];       // z j-chunks finished (target 4)
__device__ int g_rdone[MAXT];       // r j-chunks finished (target 4)
__device__ int g_cj[MAXT * 4];      // per (tile, c j-chunk) k-part count (target 4)
__device__ int g_done[MAXT];        // combine j-chunks finished (target 4)
__device__ int g_tasks[MAXTASK];
__device__ int g_ntasks;
__device__ int g_task_next;

// ============================================================
__global__ void prep_kernel(const float* __restrict__ E_bu) {
    int idx = blockIdx.x * 256 + threadIdx.x;
    if (idx < VOCAB * H) {
        int v = idx / H, h = idx - v * H;
        g_Et[idx] = E_bu[h * VOCAB + v];
    }
    if (idx < MAXT) {
        g_mem_cnt[idx] = 0; g_zdone[idx] = 0; g_rdone[idx] = 0; g_done[idx] = 0;
    }
    if (idx < MAXT * 8) g_zrj[idx] = 0;
    if (idx < MAXT * 4) g_cj[idx] = 0;
    if (idx == 0) g_task_next = 0;
}

// ============================================================
__global__ __launch_bounds__(128) void xe_kernel(const float* __restrict__ xw,
                                                 const int* __restrict__ xi) {
    __shared__ float sw[LW];
    __shared__ int si[LW];
    int n = blockIdx.x;
    int t = threadIdx.x;
    if (t < LW) { sw[t] = xw[n * LW + t]; si[t] = xi[n * LW + t]; }
    __syncthreads();
    float4 acc = make_float4(0.f, 0.f, 0.f, 0.f);
#pragma unroll 8
    for (int l = 0; l < LW; l++) {
        float w = sw[l];
        const float4 e = *(const float4*)&g_Et[si[l] * H + t * 4];
        acc.x += w * e.x; acc.y += w * e.y; acc.z += w * e.z; acc.w += w * e.w;
    }
    *(float4*)&g_xe[n * H + t * 4] = acc;
}

// ============================================================
// W-GEMMs (independent half of GRU), 128x128 tile
// ============================================================
#define BM 128
#define BN 128
#define BK 16
__global__ __launch_bounds__(256) void sgemm_nt(const float* __restrict__ B,
                                                const float* __restrict__ bias,
                                                int which) {
    const int M = NPAR;
    const float* A = g_xe + NLEAF * H;
    float* C = (which == 0) ? g_gz : (which == 1) ? g_gr : g_gh;
    __shared__ float As[BK][BM];
    __shared__ float Bs[BK][BN];
    int row0 = blockIdx.x * BM;
    int n0 = blockIdx.y * BN;
    int tid = threadIdx.x;
    int tr = tid >> 4, tc = tid & 15;

    float acc[8][8];
#pragma unroll
    for (int i = 0; i < 8; i++)
#pragma unroll
        for (int j = 0; j < 8; j++) acc[i][j] = 0.f;

    for (int k0 = 0; k0 < H; k0 += BK) {
#pragma unroll
        for (int i = 0; i < 2; i++) {
            int li = tid + i * 256;
            int m = li >> 2, kq = li & 3;
            int row = row0 + m;
            float4 f = make_float4(0.f, 0.f, 0.f, 0.f);
            if (row < M) f = *(const float4*)&A[row * H + k0 + kq * 4];
            As[kq * 4 + 0][m] = f.x; As[kq * 4 + 1][m] = f.y;
            As[kq * 4 + 2][m] = f.z; As[kq * 4 + 3][m] = f.w;
        }
#pragma unroll
        for (int i = 0; i < 2; i++) {
            int li = tid + i * 256;
            int nn = li >> 2, kq = li & 3;
            float4 f = *(const float4*)&B[(n0 + nn) * H + k0 + kq * 4];
            Bs[kq * 4 + 0][nn] = f.x; Bs[kq * 4 + 1][nn] = f.y;
            Bs[kq * 4 + 2][nn] = f.z; Bs[kq * 4 + 3][nn] = f.w;
        }
        __syncthreads();
#pragma unroll
        for (int kk = 0; kk < BK; kk++) {
            float ra[8], rb[8];
#pragma unroll
            for (int i = 0; i < 8; i++) ra[i] = As[kk][tr * 8 + i];
#pragma unroll
            for (int j = 0; j < 8; j++) rb[j] = Bs[kk][tc * 8 + j];
#pragma unroll
            for (int i = 0; i < 8; i++)
#pragma unroll
                for (int j = 0; j < 8; j++) acc[i][j] += ra[i] * rb[j];
        }
        __syncthreads();
    }
#pragma unroll
    for (int i = 0; i < 8; i++) {
        int row = row0 + tr * 8 + i;
        if (row >= M) continue;
#pragma unroll
        for (int j = 0; j < 8; j++) {
            int col = n0 + tc * 8 + j;
            C[row * H + col] = acc[i][j] + bias[col];
        }
    }
}

// ============================================================
// Levels + bucketing + task-list construction. Single block.
// ============================================================
extern __shared__ int s_dyn[];
__global__ void levels_kernel(const int* __restrict__ tree) {
    volatile int* lvl = s_dyn;
    int tid = threadIdx.x;
    int nt = blockDim.x;
    __shared__ int changed;
    __shared__ int s_maxl;
    __shared__ int cnt[MAXL + 1];
    __shared__ int tbase[MAXL + 2];
    __shared__ int toff[MAXL + 2];

    for (int p = tid; p < NPAR; p += nt) lvl[p] = 1;
    if (tid == 0) s_maxl = 1;
    __syncthreads();

    for (int it = 0; it < 4096; it++) {
        if (tid == 0) changed = 0;
        __syncthreads();
        int ch = 0;
        for (int p = tid; p < NPAR; p += nt) {
            int4 t4 = ((const int4*)tree)[p];
            int m = 1;
            int c, v;
            c = t4.x; if (c >= NLEAF) { v = lvl[c - NLEAF] + 1; if (v > m) m = v; }
            c = t4.y; if (c >= NLEAF) { v = lvl[c - NLEAF] + 1; if (v > m) m = v; }
            c = t4.z; if (c >= NLEAF) { v = lvl[c - NLEAF] + 1; if (v > m) m = v; }
            c = t4.w; if (c >= NLEAF) { v = lvl[c - NLEAF] + 1; if (v > m) m = v; }
            if (m > lvl[p]) { lvl[p] = m; ch = 1; }
        }
        if (ch) changed = 1;
        __syncthreads();
        if (!changed) break;
    }

    for (int i = tid; i <= MAXL; i += nt) cnt[i] = 0;
    __syncthreads();
    int mymax = 1;
    for (int p = tid; p < NPAR; p += nt) {
        int l = lvl[p]; if (l > MAXL) l = MAXL;
        atomicAdd(&cnt[l], 1);
        if (l > mymax) mymax = l;
    }
    atomicMax(&s_maxl, mymax);
    __syncthreads();
    if (tid == 0) {
        int acc = 0;
        for (int l = 0; l <= MAXL; l++) { g_lstart[l] = acc; acc += cnt[l]; }
        g_lstart[MAXL + 1] = acc;
        g_nlev = s_maxl;
    }
    __syncthreads();
    for (int i = tid; i <= MAXL; i += nt) cnt[i] = g_lstart[i];
    __syncthreads();
    for (int p = tid; p < NPAR; p += nt) {
        int l = lvl[p]; if (l > MAXL) l = MAXL;
        int pos = atomicAdd(&cnt[l], 1);
        g_order[pos] = p;
        g_lvl[p] = l;
    }
    __syncthreads();

    // ---- tile + task construction ----
    int nlev = s_maxl;
    if (tid == 0) {
        int tb = 0, to = 0;
        for (int l = 1; l <= nlev; l++) {
            int Nl = g_lstart[l + 1] - g_lstart[l];
            int ntl = (Nl + 63) >> 6;
            tbase[l] = tb;
            toff[l] = to;
            tb += ntl;
            to += Nl + SUBT * ntl;
        }
        tbase[nlev + 1] = tb;
        g_ntasks = to;
    }
    __syncthreads();

    for (int i = tid; i < NPAR; i += nt) {
        int p = g_order[i];
        int l = g_lvl[p];
        int loc = i - g_lstart[l];
        g_tasks[toff[l] + loc] = i;
        g_ptile[p] = tbase[l] + (loc >> 6);
    }
    for (int l = 1; l <= nlev; l++) {
        int ls = g_lstart[l];
        int Nl = g_lstart[l + 1] - ls;
        int ntl = (Nl + 63) >> 6;
        for (int lt = tid; lt < ntl; lt += nt) {
            int tile = tbase[l] + lt;
            int start = ls + lt * 64;
            int c = Nl - lt * 64; if (c > 64) c = 64;
            g_tile_start[tile] = start;
            g_tile_cnt[tile] = c;
            int tb0 = toff[l] + Nl + lt * SUBT;
#pragma unroll
            for (int s = 0; s < SUBT; s++) g_tasks[tb0 + s] = NPAR + tile * SUBT + s;
        }
    }
}

// ============================================================
// Persistent task-queue wavefront kernel
// ============================================================
struct ShA {
    float bufA[DEG][H];
    float bufB[DEG][H];
    float sc[HEADS][DEG][DEG];
    int cidx[DEG];
    int nc;
};
struct ShB {
    float As[16][64];
    float Bs[16][128];
    int pidx[64];
};

__device__ __forceinline__ void spin_ge(volatile int* addr, int target) {
    while (*addr < target) __nanosleep(64);
}

// 64 x 128 output partial over K=128, accumulated via atomicAdd into C.
__device__ void partial_tile(ShB* sb, int i0, int mtile,
                             const float* __restrict__ Asrc,
                             const float* __restrict__ Bsrc,  // U + jbase*H
                             float* __restrict__ Cdst, int jbase, int kbase) {
    int tid = threadIdx.x;
    if (tid < 64) sb->pidx[tid] = g_order[i0 + ((tid < mtile) ? tid : 0)];
    __syncthreads();

    float acc[4][8];
#pragma unroll
    for (int a = 0; a < 4; a++)
#pragma unroll
        for (int b = 0; b < 8; b++) acc[a][b] = 0.f;

    int tr = tid >> 4, tc = tid & 15;

    for (int k0 = kbase; k0 < kbase + 128; k0 += 16) {
        {
            int i = tid >> 2, kq = tid & 3;
            float4 f = *(const float4*)&Asrc[(size_t)sb->pidx[i] * H + k0 + kq * 4];
            sb->As[kq * 4 + 0][i] = f.x; sb->As[kq * 4 + 1][i] = f.y;
            sb->As[kq * 4 + 2][i] = f.z; sb->As[kq * 4 + 3][i] = f.w;
        }
#pragma unroll
        for (int e = 0; e < 2; e++) {
            int li = tid + e * 256;
            int nn = li >> 2, kq = li & 3;
            float4 f = *(const float4*)&Bsrc[(size_t)nn * H + k0 + kq * 4];
            sb->Bs[kq * 4 + 0][nn] = f.x; sb->Bs[kq * 4 + 1][nn] = f.y;
            sb->Bs[kq * 4 + 2][nn] = f.z; sb->Bs[kq * 4 + 3][nn] = f.w;
        }
        __syncthreads();
#pragma unroll
        for (int kk = 0; kk < 16; kk++) {
            float ra[4], rb[8];
#pragma unroll
            for (int a = 0; a < 4; a++) ra[a] = sb->As[kk][tr * 4 + a];
#pragma unroll
            for (int b = 0; b < 8; b++) rb[b] = sb->Bs[kk][tc * 8 + b];
#pragma unroll
            for (int a = 0; a < 4; a++)
#pragma unroll
                for (int b = 0; b < 8; b++) acc[a][b] += ra[a] * rb[b];
        }
        __syncthreads();
    }

#pragma unroll
    for (int a = 0; a < 4; a++) {
        int i = tr * 4 + a;
        if (i >= mtile) continue;
        size_t pbase = (size_t)sb->pidx[i] * H + jbase;
#pragma unroll
        for (int b = 0; b < 8; b++) atomicAdd(&Cdst[pbase + tc * 8 + b], acc[a][b]);
    }
    __syncthreads();
}

__device__ __forceinline__ void do_attn(ShA* sa, int p, const int* __restrict__ tree) {
    int tid = threadIdx.x;
    if (tid == 0) {
        int nc = 0;
#pragma unroll
        for (int j = 0; j < DEG; j++) {
            int c = tree[p * DEG + j];
            if (c > -1) sa->cidx[nc++] = c;
        }
        sa->nc = nc;
    }
    __syncthreads();
    int nc = sa->nc;

    if (tid < nc) {
        int c = sa->cidx[tid];
        if (c >= NLEAF) spin_ge(&g_done[g_ptile[c - NLEAF]], 4);
    }
    __syncthreads();
    __threadfence();

    for (int i = 0; i < nc; i++) {
        int c = sa->cidx[i];
        const float* src = (c < NLEAF) ? &g_xe[(size_t)c * H]
                                       : &g_ph[(size_t)(c - NLEAF) * H];
        if (tid < 128) ((float4*)sa->bufA[i])[tid] = ((const float4*)src)[tid];
    }
    __syncthreads();

    float (*cur)[H] = sa->bufA;
    float (*nxt)[H] = sa->bufB;

    for (int layer = 0; layer < NLAYER; layer++) {
        int tot = HEADS * nc * nc;
        for (int t = tid; t < tot; t += 256) {
            int hd = t / (nc * nc);
            int r2 = t - hd * nc * nc;
            int q = r2 / nc, k = r2 - q * nc;
            const float* qp = &cur[q][hd * DK];
            const float* kp = &cur[k][hd * DK];
            float s = 0.f;
#pragma unroll 16
            for (int d = 0; d < DK; d++) s += qp[d] * kp[d];
            sa->sc[hd][q][k] = s * 0.125f;
        }
        __syncthreads();
        for (int t = tid; t < HEADS * nc; t += 256) {
            int hd = t / nc, q = t - hd * nc;
            float m = -1e30f;
            for (int k = 0; k < nc; k++) m = fmaxf(m, sa->sc[hd][q][k]);
            float ssum = 0.f;
            for (int k = 0; k < nc; k++) {
                float e = expf(sa->sc[hd][q][k] - m);
                ssum += e;
                sa->sc[hd][q][k] = e;
            }
            float inv = 1.0f / ssum;
            for (int k = 0; k < nc; k++) sa->sc[hd][q][k] *= inv;
        }
        __syncthreads();
        for (int c = tid; c < H; c += 256) {
            int hd = c >> 6;
            for (int q = 0; q < nc; q++) {
                float o = 0.f;
                for (int k = 0; k < nc; k++) o += sa->sc[hd][q][k] * cur[k][c];
                nxt[q][c] = o;
            }
        }
        __syncthreads();
        float (*tmp)[H] = cur; cur = nxt; nxt = tmp;
    }
    float invn = 1.0f / (float)nc;
    for (int c = tid; c < H; c += 256) {
        float s = 0.f;
        for (int q = 0; q < nc; q++) s += cur[q][c];
        g_mem[(size_t)p * H + c] = s * invn;
    }
    __syncthreads();
}

__global__ __launch_bounds__(256) void wave_kernel(const int* __restrict__ tree,
                                                   const float* __restrict__ Uz,
                                                   const float* __restrict__ Ur,
                                                   const float* __restrict__ Uh) {
    __shared__ union { ShA a; ShB b; } sh;
    __shared__ int s_task;
    __shared__ int s_fin;
    int tid = threadIdx.x;
    int ntasks = g_ntasks;

    while (true) {
        if (tid == 0) s_task = atomicAdd(&g_task_next, 1);
        __syncthreads();
        int t = s_task;
        if (t >= ntasks) break;
        int v = g_tasks[t];
        if (v < NPAR) {
            int p = g_order[v];
            do_attn(&sh.a, p, tree);
            __threadfence();
            __syncthreads();
            if (tid == 0) atomicAdd(&g_mem_cnt[g_ptile[p]], 1);
        } else {
            int b = v - NPAR;
            int tile = b / SUBT;
            int sub = b - tile * SUBT;
            int i0 = g_tile_start[tile];
            int mtile = g_tile_cnt[tile];
            if (sub < 32) {
                // z/r partial: j 0-3 -> z, 4-7 -> r; kc = sub&3
                int j = sub >> 2, kc = sub & 3;
                if (tid == 0) spin_ge(&g_mem_cnt[tile], mtile);
                __syncthreads();
                __threadfence();
                const float* U; float* C; int jbase;
                if (j < 4) { U = Uz; C = g_gz; jbase = j * 128; }
                else       { U = Ur; C = g_gr; jbase = (j - 4) * 128; }
                partial_tile(&sh.b, i0, mtile, g_mem, U + (size_t)jbase * H, C,
                             jbase, kc * 128);
                __threadfence();
                if (tid == 0) { int old = atomicAdd(&g_zrj[tile * 8 + j], 1); s_fin = (old == 3); }
                __syncthreads();
                if (s_fin) {
                    __threadfence();
                    if (j < 4) {
                        for (int e = tid; e < mtile * 128; e += 256) {
                            int i = e >> 7, c = jbase + (e & 127);
                            size_t a = (size_t)sh.b.pidx[i] * H + c;
                            g_gz[a] = 1.0f / (1.0f + expf(-g_gz[a]));
                        }
                        __threadfence();
                        __syncthreads();
                        if (tid == 0) atomicAdd(&g_zdone[tile], 1);
                    } else {
                        for (int e = tid; e < mtile * 128; e += 256) {
                            int i = e >> 7, c = jbase + (e & 127);
                            size_t a = (size_t)sh.b.pidx[i] * H + c;
                            float r = 1.0f / (1.0f + expf(-g_gr[a]));
                            g_gr[a] = g_mem[a] * r;
                        }
                        __threadfence();
                        __syncthreads();
                        if (tid == 0) atomicAdd(&g_rdone[tile], 1);
                    }
                }
            } else {
                // c partial: j 0-3, kc
                int s2 = sub - 32;
                int j = s2 >> 2, kc = s2 & 3;
                int jbase = j * 128;
                if (tid == 0) spin_ge(&g_rdone[tile], 4);
                __syncthreads();
                __threadfence();
                partial_tile(&sh.b, i0, mtile, g_gr, Uh + (size_t)jbase * H, g_gh,
                             jbase, kc * 128);
                __threadfence();
                if (tid == 0) { int old = atomicAdd(&g_cj[tile * 4 + j], 1); s_fin = (old == 3); }
                __syncthreads();
                if (s_fin) {
                    if (tid == 0) spin_ge(&g_zdone[tile], 4);
                    __syncthreads();
                    __threadfence();
                    for (int e = tid; e < mtile * 128; e += 256) {
                        int i = e >> 7, c = jbase + (e & 127);
                        size_t a = (size_t)sh.b.pidx[i] * H + c;
                        float cc = tanhf(g_gh[a]);
                        float z = g_gz[a];
                        float m = g_mem[a];
                        g_ph[a] = z * m + (1.0f - z) * cc;
                    }
                    __threadfence();
                    __syncthreads();
                    if (tid == 0) atomicAdd(&g_done[tile], 1);
                }
            }
        }
        __syncthreads();
    }
}

// ============================================================
__global__ void maxk_kernel() {
    int b = blockIdx.x;
    int rows_per = (NPAR + MAXB - 1) / MAXB;
    int r0 = b * rows_per;
    int r1 = min(NPAR, r0 + rows_per);
    for (int c = threadIdx.x; c < H; c += 256) {
        float m = -1e30f;
        for (int r = r0; r < r1; r++) m = fmaxf(m, g_ph[r * H + c]);
        g_pmax[b * H + c] = m;
    }
}

__global__ __launch_bounds__(512) void final_kernel(const float* __restrict__ Wout,
                                                    const float* __restrict__ bout,
                                                    float* __restrict__ out) {
    __shared__ float fin[H];
    __shared__ float logits[NCLASS];
    int tid = threadIdx.x;
    if (tid < H) {
        float m = -1e30f;
        for (int b = 0; b < MAXB; b++) m = fmaxf(m, g_pmax[b * H + tid]);
        fin[tid] = m;
    }
    __syncthreads();
    if (tid < NCLASS * 32) {
        int cls = tid >> 5, lane = tid & 31;
        float s = 0.f;
        for (int h = lane; h < H; h += 32) s += Wout[cls * H + h] * fin[h];
#pragma unroll
        for (int o = 16; o > 0; o >>= 1) s += __shfl_down_sync(0xffffffffu, s, o);
        if (lane == 0) logits[cls] = s + bout[cls];
    }
    __syncthreads();
    if (tid == 0) {
        float m = fmaxf(fmaxf(logits[0], logits[1]), fmaxf(logits[2], logits[3]));
        float e0 = expf(logits[0] - m), e1 = expf(logits[1] - m);
        float e2 = expf(logits[2] - m), e3 = expf(logits[3] - m);
        float inv = 1.0f / (e0 + e1 + e2 + e3);
        out[0] = e0 * inv; out[1] = e1 * inv; out[2] = e2 * inv; out[3] = e3 * inv;
    }
}

// ============================================================
extern "C" void kernel_launch(void* const* d_in, const int* in_sizes, int n_in,
                              void* d_out, int out_size) {
    const float* xw   = (const float*)d_in[0];
    const int*   xi   = (const int*)d_in[1];
    const int*   tree = (const int*)d_in[2];
    const float* E    = (const float*)d_in[3];
    const float* Wz   = (const float*)d_in[4];
    const float* Uz   = (const float*)d_in[5];
    const float* bz   = (const float*)d_in[6];
    const float* Wr   = (const float*)d_in[7];
    const float* Ur   = (const float*)d_in[8];
    const float* br   = (const float*)d_in[9];
    const float* Wh   = (const float*)d_in[10];
    const float* Uh   = (const float*)d_in[11];
    const float* bh   = (const float*)d_in[12];
    const float* Wout = (const float*)d_in[13];
    const float* bout = (const float*)d_in[14];

    cudaFuncSetAttribute(levels_kernel,
                         cudaFuncAttributeMaxDynamicSharedMemorySize, NPAR * 4 + 1024);
    int nsm = 0;
    cudaDeviceGetAttribute(&nsm, cudaDevAttrMultiProcessorCount, 0);
    if (nsm <= 0) nsm = 148;
    int grid = 2 * nsm;   // 2 blocks/SM: minimizes GEMM-partial latency collisions

    prep_kernel<<<(VOCAB * H + 255) / 256, 256>>>(E);
    xe_kernel<<<NTOT, 128>>>(xw, xi);

    dim3 gg((NPAR + BM - 1) / BM, H / BN);
    sgemm_nt<<<gg, 256>>>(Wz, bz, 0);
    sgemm_nt<<<gg, 256>>>(Wr, br, 1);
    sgemm_nt<<<gg, 256>>>(Wh, bh, 2);

    levels_kernel<<<1, 1024, NPAR * 4>>>(tree);
    wave_kernel<<<grid, 256>>>(tree, Uz, Ur, Uh);

    maxk_kernel<<<MAXB, 256>>>();
    final_kernel<<<1, 512>>>(Wout, bout, (float*)d_out);
    (void)in_sizes; (void)n_in; (void)out_size;
}

// round 6
// speedup vs baseline: 1.1958x; 1.1958x over previous
#include <cuda_runtime.h>
#include <math.h>

#define H 512
#define HEADS 8
#define DK 64
#define NCLASS 4
#define VOCAB 5000
#define LW 32
#define NLEAF 20000
#define NPAR 20000
#define NTOT (NLEAF + NPAR)
#define DEG 4
#define NLAYER 5
#define MAXB 64
#define MAXL 512
#define MAXGRID 1024

// ---- static device scratch ----
__device__ float g_Et[VOCAB * H];
__device__ float g_xe[NTOT * H];
__device__ float g_gz[NPAR * H];   // Wz@xe+bz -> z after B1
__device__ float g_gr[NPAR * H];   // Wr@xe+br -> mem*r after B1
__device__ float g_gh[NPAR * H];   // Wh@xe+bh
__device__ float g_mem[NPAR * H];
__device__ float g_ph[NPAR * H];
__device__ float g_pmax[MAXB * H];

__device__ int g_lvl[NPAR];
__device__ int g_lstart[MAXL + 2];
__device__ int g_nlev;
__device__ int g_order[NPAR];

// flag-array barrier
__device__ volatile int g_arr[MAXGRID];
__device__ volatile int g_gen;

// ============================================================
__global__ void prep_kernel(const float* __restrict__ E_bu) {
    int idx = blockIdx.x * 256 + threadIdx.x;
    if (idx < VOCAB * H) {
        int v = idx / H, h = idx - v * H;
        g_Et[idx] = E_bu[h * VOCAB + v];
    }
    if (idx < MAXGRID) g_arr[idx] = 0;
    if (idx == 0) g_gen = 0;
}

// ============================================================
__global__ __launch_bounds__(128) void xe_kernel(const float* __restrict__ xw,
                                                 const int* __restrict__ xi) {
    __shared__ float sw[LW];
    __shared__ int si[LW];
    int n = blockIdx.x;
    int t = threadIdx.x;
    if (t < LW) { sw[t] = xw[n * LW + t]; si[t] = xi[n * LW + t]; }
    __syncthreads();
    float4 acc = make_float4(0.f, 0.f, 0.f, 0.f);
#pragma unroll 8
    for (int l = 0; l < LW; l++) {
        float w = sw[l];
        const float4 e = *(const float4*)&g_Et[si[l] * H + t * 4];
        acc.x += w * e.x; acc.y += w * e.y; acc.z += w * e.z; acc.w += w * e.w;
    }
    *(float4*)&g_xe[n * H + t * 4] = acc;
}

// ============================================================
// W-GEMMs (independent half of GRU), 128x128 tile
// ============================================================
#define BM 128
#define BN 128
#define BK 16
__global__ __launch_bounds__(256) void sgemm_nt(const float* __restrict__ B,
                                                const float* __restrict__ bias,
                                                int which) {
    const int M = NPAR;
    const float* A = g_xe + NLEAF * H;
    float* C = (which == 0) ? g_gz : (which == 1) ? g_gr : g_gh;
    __shared__ float As[BK][BM];
    __shared__ float Bs[BK][BN];
    int row0 = blockIdx.x * BM;
    int n0 = blockIdx.y * BN;
    int tid = threadIdx.x;
    int tr = tid >> 4, tc = tid & 15;

    float acc[8][8];
#pragma unroll
    for (int i = 0; i < 8; i++)
#pragma unroll
        for (int j = 0; j < 8; j++) acc[i][j] = 0.f;

    for (int k0 = 0; k0 < H; k0 += BK) {
#pragma unroll
        for (int i = 0; i < 2; i++) {
            int li = tid + i * 256;
            int m = li >> 2, kq = li & 3;
            int row = row0 + m;
            float4 f = make_float4(0.f, 0.f, 0.f, 0.f);
            if (row < M) f = *(const float4*)&A[row * H + k0 + kq * 4];
            As[kq * 4 + 0][m] = f.x; As[kq * 4 + 1][m] = f.y;
            As[kq * 4 + 2][m] = f.z; As[kq * 4 + 3][m] = f.w;
        }
#pragma unroll
        for (int i = 0; i < 2; i++) {
            int li = tid + i * 256;
            int nn = li >> 2, kq = li & 3;
            float4 f = *(const float4*)&B[(n0 + nn) * H + k0 + kq * 4];
            Bs[kq * 4 + 0][nn] = f.x; Bs[kq * 4 + 1][nn] = f.y;
            Bs[kq * 4 + 2][nn] = f.z; Bs[kq * 4 + 3][nn] = f.w;
        }
        __syncthreads();
#pragma unroll
        for (int kk = 0; kk < BK; kk++) {
            float ra[8], rb[8];
#pragma unroll
            for (int i = 0; i < 8; i++) ra[i] = As[kk][tr * 8 + i];
#pragma unroll
            for (int j = 0; j < 8; j++) rb[j] = Bs[kk][tc * 8 + j];
#pragma unroll
            for (int i = 0; i < 8; i++)
#pragma unroll
                for (int j = 0; j < 8; j++) acc[i][j] += ra[i] * rb[j];
        }
        __syncthreads();
    }
#pragma unroll
    for (int i = 0; i < 8; i++) {
        int row = row0 + tr * 8 + i;
        if (row >= M) continue;
#pragma unroll
        for (int j = 0; j < 8; j++) {
            int col = n0 + tc * 8 + j;
            C[row * H + col] = acc[i][j] + bias[col];
        }
    }
}

// ============================================================
// Levels + bucketing. Single block, 1024 threads.
// ============================================================
extern __shared__ int s_dyn[];
__global__ void levels_kernel(const int* __restrict__ tree) {
    volatile int* lvl = s_dyn;
    int tid = threadIdx.x;
    int nt = blockDim.x;
    __shared__ int changed;
    __shared__ int s_maxl;
    __shared__ int cnt[MAXL + 1];

    for (int p = tid; p < NPAR; p += nt) lvl[p] = 1;
    if (tid == 0) s_maxl = 1;
    __syncthreads();

    for (int it = 0; it < 4096; it++) {
        if (tid == 0) changed = 0;
        __syncthreads();
        int ch = 0;
        for (int p = tid; p < NPAR; p += nt) {
            int4 t4 = ((const int4*)tree)[p];
            int m = 1;
            int c, v;
            c = t4.x; if (c >= NLEAF) { v = lvl[c - NLEAF] + 1; if (v > m) m = v; }
            c = t4.y; if (c >= NLEAF) { v = lvl[c - NLEAF] + 1; if (v > m) m = v; }
            c = t4.z; if (c >= NLEAF) { v = lvl[c - NLEAF] + 1; if (v > m) m = v; }
            c = t4.w; if (c >= NLEAF) { v = lvl[c - NLEAF] + 1; if (v > m) m = v; }
            if (m > lvl[p]) { lvl[p] = m; ch = 1; }
        }
        if (ch) changed = 1;
        __syncthreads();
        if (!changed) break;
    }

    for (int i = tid; i <= MAXL; i += nt) cnt[i] = 0;
    __syncthreads();
    int mymax = 1;
    for (int p = tid; p < NPAR; p += nt) {
        int l = lvl[p]; if (l > MAXL) l = MAXL;
        atomicAdd(&cnt[l], 1);
        if (l > mymax) mymax = l;
    }
    atomicMax(&s_maxl, mymax);
    __syncthreads();
    if (tid == 0) {
        int acc = 0;
        for (int l = 0; l <= MAXL; l++) { g_lstart[l] = acc; acc += cnt[l]; }
        g_lstart[MAXL + 1] = acc;
        g_nlev = s_maxl;
    }
    __syncthreads();
    for (int i = tid; i <= MAXL; i += nt) cnt[i] = g_lstart[i];
    __syncthreads();
    for (int p = tid; p < NPAR; p += nt) {
        int l = lvl[p]; if (l > MAXL) l = MAXL;
        int pos = atomicAdd(&cnt[l], 1);
        g_order[pos] = p;
        g_lvl[p] = l;
    }
}

// ============================================================
// Persistent wavefront kernel: barrier per phase, small GEMM tiles.
// ============================================================
struct ShA {
    float bufA[DEG][H];
    float bufB[DEG][H];
    float sc[HEADS][DEG][DEG];
    int cidx[DEG];
    int nc;
};
struct ShB {
    float As[16][32];
    float Bs[16][64];
    int pidx[32];
};

// flag-array sense barrier: no atomics, block0 scans in parallel
__device__ __forceinline__ void grid_sync2(int bid, int nb, int& cnt) {
    cnt++;
    __threadfence();
    __syncthreads();
    if (threadIdx.x == 0) g_arr[bid] = cnt;
    if (bid == 0) {
        for (int i = threadIdx.x; i < nb; i += blockDim.x) {
            while (g_arr[i] < cnt) __nanosleep(32);
        }
        __syncthreads();
        if (threadIdx.x == 0) { __threadfence(); g_gen = cnt; }
    } else {
        if (threadIdx.x == 0) {
            while (g_gen < cnt) __nanosleep(32);
            __threadfence();
        }
    }
    __syncthreads();
}

// 32 x 64 output tile, full K=512, direct-store epilogues.
// PHASE 1: jbase in [0,1024): <512 -> z (sigmoid), >=512 -> r (mem*r)
// PHASE 2: jbase in [0,512): c (tanh) + final combine
template <int PHASE>
__device__ void gemm_tile(ShB* sb, int i0, int mtile, int jbase,
                          const float* __restrict__ Uz,
                          const float* __restrict__ Ur,
                          const float* __restrict__ Uh) {
    int tid = threadIdx.x;
    if (tid < 32) sb->pidx[tid] = g_order[i0 + ((tid < mtile) ? tid : 0)];
    __syncthreads();

    const float* Asrc = (PHASE == 1) ? g_mem : g_gr;
    const float* Bsrc;
    if (PHASE == 1) Bsrc = (jbase < H) ? (Uz + (size_t)jbase * H)
                                       : (Ur + (size_t)(jbase - H) * H);
    else            Bsrc = Uh + (size_t)jbase * H;

    float acc[2][4];
#pragma unroll
    for (int a = 0; a < 2; a++)
#pragma unroll
        for (int b = 0; b < 4; b++) acc[a][b] = 0.f;

    int tr = tid >> 4, tc = tid & 15;

    for (int k0 = 0; k0 < H; k0 += 16) {
        if (tid < 128) {
            int row = tid >> 2, kq = tid & 3;
            float4 f = *(const float4*)&Asrc[(size_t)sb->pidx[row] * H + k0 + kq * 4];
            sb->As[kq * 4 + 0][row] = f.x; sb->As[kq * 4 + 1][row] = f.y;
            sb->As[kq * 4 + 2][row] = f.z; sb->As[kq * 4 + 3][row] = f.w;
        }
        {
            int nn = tid >> 2, kq = tid & 3;
            float4 f = *(const float4*)&Bsrc[(size_t)nn * H + k0 + kq * 4];
            sb->Bs[kq * 4 + 0][nn] = f.x; sb->Bs[kq * 4 + 1][nn] = f.y;
            sb->Bs[kq * 4 + 2][nn] = f.z; sb->Bs[kq * 4 + 3][nn] = f.w;
        }
        __syncthreads();
#pragma unroll
        for (int kk = 0; kk < 16; kk++) {
            float2 ra = *(const float2*)&sb->As[kk][tr * 2];
            float4 rb = *(const float4*)&sb->Bs[kk][tc * 4];
            acc[0][0] += ra.x * rb.x; acc[0][1] += ra.x * rb.y;
            acc[0][2] += ra.x * rb.z; acc[0][3] += ra.x * rb.w;
            acc[1][0] += ra.y * rb.x; acc[1][1] += ra.y * rb.y;
            acc[1][2] += ra.y * rb.z; acc[1][3] += ra.y * rb.w;
        }
        __syncthreads();
    }

#pragma unroll
    for (int a = 0; a < 2; a++) {
        int i = tr * 2 + a;
        if (i >= mtile) continue;
        size_t pbase = (size_t)sb->pidx[i] * H;
#pragma unroll
        for (int b = 0; b < 4; b++) {
            int col = jbase + tc * 4 + b;
            float v = acc[a][b];
            if (PHASE == 1) {
                if (jbase < H) {
                    g_gz[pbase + col] = 1.0f / (1.0f + expf(-(v + g_gz[pbase + col])));
                } else {
                    int c2 = col - H;
                    float r = 1.0f / (1.0f + expf(-(v + g_gr[pbase + c2])));
                    g_gr[pbase + c2] = g_mem[pbase + c2] * r;
                }
            } else {
                float cc = tanhf(v + g_gh[pbase + col]);
                float z = g_gz[pbase + col];
                float m = g_mem[pbase + col];
                g_ph[pbase + col] = z * m + (1.0f - z) * cc;
            }
        }
    }
    __syncthreads();
}

__device__ __forceinline__ void do_attn(ShA* sa, int p, const int* __restrict__ tree) {
    int tid = threadIdx.x;
    if (tid == 0) {
        int nc = 0;
#pragma unroll
        for (int j = 0; j < DEG; j++) {
            int c = tree[p * DEG + j];
            if (c > -1) sa->cidx[nc++] = c;
        }
        sa->nc = nc;
    }
    __syncthreads();
    int nc = sa->nc;

    for (int i = 0; i < nc; i++) {
        int c = sa->cidx[i];
        const float* src = (c < NLEAF) ? &g_xe[(size_t)c * H]
                                       : &g_ph[(size_t)(c - NLEAF) * H];
        if (tid < 128) ((float4*)sa->bufA[i])[tid] = ((const float4*)src)[tid];
    }
    __syncthreads();

    float (*cur)[H] = sa->bufA;
    float (*nxt)[H] = sa->bufB;

    for (int layer = 0; layer < NLAYER; layer++) {
        int tot = HEADS * nc * nc;
        for (int t = tid; t < tot; t += 256) {
            int hd = t / (nc * nc);
            int r2 = t - hd * nc * nc;
            int q = r2 / nc, k = r2 - q * nc;
            const float* qp = &cur[q][hd * DK];
            const float* kp = &cur[k][hd * DK];
            float s = 0.f;
#pragma unroll 16
            for (int d = 0; d < DK; d++) s += qp[d] * kp[d];
            sa->sc[hd][q][k] = s * 0.125f;
        }
        __syncthreads();
        for (int t = tid; t < HEADS * nc; t += 256) {
            int hd = t / nc, q = t - hd * nc;
            float m = -1e30f;
            for (int k = 0; k < nc; k++) m = fmaxf(m, sa->sc[hd][q][k]);
            float ssum = 0.f;
            for (int k = 0; k < nc; k++) {
                float e = expf(sa->sc[hd][q][k] - m);
                ssum += e;
                sa->sc[hd][q][k] = e;
            }
            float inv = 1.0f / ssum;
            for (int k = 0; k < nc; k++) sa->sc[hd][q][k] *= inv;
        }
        __syncthreads();
        for (int c = tid; c < H; c += 256) {
            int hd = c >> 6;
            for (int q = 0; q < nc; q++) {
                float o = 0.f;
                for (int k = 0; k < nc; k++) o += sa->sc[hd][q][k] * cur[k][c];
                nxt[q][c] = o;
            }
        }
        __syncthreads();
        float (*tmp)[H] = cur; cur = nxt; nxt = tmp;
    }
    float invn = 1.0f / (float)nc;
    for (int c = tid; c < H; c += 256) {
        float s = 0.f;
        for (int q = 0; q < nc; q++) s += cur[q][c];
        g_mem[(size_t)p * H + c] = s * invn;
    }
    __syncthreads();
}

__global__ __launch_bounds__(256) void wave_kernel(const int* __restrict__ tree,
                                                   const float* __restrict__ Uz,
                                                   const float* __restrict__ Ur,
                                                   const float* __restrict__ Uh) {
    __shared__ union { ShA a; ShB b; } sh;
    int bid = blockIdx.x;
    int nb = gridDim.x;
    int nlev = g_nlev;
    int cnt = 0;

    for (int l = 1; l <= nlev; l++) {
        int ls = g_lstart[l];
        int le = g_lstart[l + 1];
        int Nl = le - ls;

        // ---- Phase A: attention + memory ----
        for (int ii = ls + bid; ii < le; ii += nb) {
            do_attn(&sh.a, g_order[ii], tree);
        }
        grid_sync2(bid, nb, cnt);

        // ---- Phase B1: z,r GEMM (tiles 32 parents x 64 cols of 1024) ----
        int pt32 = (Nl + 31) >> 5;
        int ntiles = pt32 * 16;
        for (int t = bid; t < ntiles; t += nb) {
            int pt = t >> 4;
            int jbase = (t & 15) * 64;
            int i0 = ls + pt * 32;
            int mtile = Nl - pt * 32; if (mtile > 32) mtile = 32;
            gemm_tile<1>(&sh.b, i0, mtile, jbase, Uz, Ur, Uh);
        }
        grid_sync2(bid, nb, cnt);

        // ---- Phase B2: c GEMM + combine (tiles 32 x 64 of 512) ----
        ntiles = pt32 * 8;
        for (int t = bid; t < ntiles; t += nb) {
            int pt = t >> 3;
            int jbase = (t & 7) * 64;
            int i0 = ls + pt * 32;
            int mtile = Nl - pt * 32; if (mtile > 32) mtile = 32;
            gemm_tile<2>(&sh.b, i0, mtile, jbase, Uz, Ur, Uh);
        }
        grid_sync2(bid, nb, cnt);
    }
}

// ============================================================
__global__ void maxk_kernel() {
    int b = blockIdx.x;
    int rows_per = (NPAR + MAXB - 1) / MAXB;
    int r0 = b * rows_per;
    int r1 = min(NPAR, r0 + rows_per);
    for (int c = threadIdx.x; c < H; c += 256) {
        float m = -1e30f;
        for (int r = r0; r < r1; r++) m = fmaxf(m, g_ph[r * H + c]);
        g_pmax[b * H + c] = m;
    }
}

__global__ __launch_bounds__(512) void final_kernel(const float* __restrict__ Wout,
                                                    const float* __restrict__ bout,
                                                    float* __restrict__ out) {
    __shared__ float fin[H];
    __shared__ float logits[NCLASS];
    int tid = threadIdx.x;
    if (tid < H) {
        float m = -1e30f;
        for (int b = 0; b < MAXB; b++) m = fmaxf(m, g_pmax[b * H + tid]);
        fin[tid] = m;
    }
    __syncthreads();
    if (tid < NCLASS * 32) {
        int cls = tid >> 5, lane = tid & 31;
        float s = 0.f;
        for (int h = lane; h < H; h += 32) s += Wout[cls * H + h] * fin[h];
#pragma unroll
        for (int o = 16; o > 0; o >>= 1) s += __shfl_down_sync(0xffffffffu, s, o);
        if (lane == 0) logits[cls] = s + bout[cls];
    }
    __syncthreads();
    if (tid == 0) {
        float m = fmaxf(fmaxf(logits[0], logits[1]), fmaxf(logits[2], logits[3]));
        float e0 = expf(logits[0] - m), e1 = expf(logits[1] - m);
        float e2 = expf(logits[2] - m), e3 = expf(logits[3] - m);
        float inv = 1.0f / (e0 + e1 + e2 + e3);
        out[0] = e0 * inv; out[1] = e1 * inv; out[2] = e2 * inv; out[3] = e3 * inv;
    }
}

// ============================================================
extern "C" void kernel_launch(void* const* d_in, const int* in_sizes, int n_in,
                              void* d_out, int out_size) {
    const float* xw   = (const float*)d_in[0];
    const int*   xi   = (const int*)d_in[1];
    const int*   tree = (const int*)d_in[2];
    const float* E    = (const float*)d_in[3];
    const float* Wz   = (const float*)d_in[4];
    const float* Uz   = (const float*)d_in[5];
    const float* bz   = (const float*)d_in[6];
    const float* Wr   = (const float*)d_in[7];
    const float* Ur   = (const float*)d_in[8];
    const float* br   = (const float*)d_in[9];
    const float* Wh   = (const float*)d_in[10];
    const float* Uh   = (const float*)d_in[11];
    const float* bh   = (const float*)d_in[12];
    const float* Wout = (const float*)d_in[13];
    const float* bout = (const float*)d_in[14];

    cudaFuncSetAttribute(levels_kernel,
                         cudaFuncAttributeMaxDynamicSharedMemorySize, NPAR * 4 + 1024);
    int perSM = 0;
    cudaOccupancyMaxActiveBlocksPerMultiprocessor(&perSM, wave_kernel, 256, 0);
    if (perSM < 1) perSM = 1;
    if (perSM > 4) perSM = 4;
    int nsm = 0;
    cudaDeviceGetAttribute(&nsm, cudaDevAttrMultiProcessorCount, 0);
    if (nsm <= 0) nsm = 148;
    int grid = perSM * nsm;
    if (grid > MAXGRID) grid = MAXGRID;

    prep_kernel<<<(VOCAB * H + 255) / 256, 256>>>(E);
    xe_kernel<<<NTOT, 128>>>(xw, xi);

    dim3 gg((NPAR + BM - 1) / BM, H / BN);
    sgemm_nt<<<gg, 256>>>(Wz, bz, 0);
    sgemm_nt<<<gg, 256>>>(Wr, br, 1);
    sgemm_nt<<<gg, 256>>>(Wh, bh, 2);

    levels_kernel<<<1, 1024, NPAR * 4>>>(tree);
    wave_kernel<<<grid, 256>>>(tree, Uz, Ur, Uh);

    maxk_kernel<<<MAXB, 256>>>();
    final_kernel<<<1, 512>>>(Wout, bout, (float*)d_out);
    (void)in_sizes; (void)n_in; (void)out_size;
}

// round 8
// speedup vs baseline: 1.2340x; 1.0319x over previous
#include <cuda_runtime.h>
#include <math.h>

#define H 512
#define HEADS 8
#define DK 64
#define NCLASS 4
#define VOCAB 5000
#define LW 32
#define NLEAF 20000
#define NPAR 20000
#define NTOT (NLEAF + NPAR)
#define DEG 4
#define NLAYER 5
#define MAXB 64
#define MAXL 512
#define MAXGRID 1024
#define NROWS 1536           // 512 Uz + 512 Ur + 512 Uh
#define RPB_MAX 8            // max U rows cached per block

// ---- static device scratch ----
__device__ float g_Et[VOCAB * H];
__device__ float g_xe[NTOT * H];
__device__ float g_gz[NPAR * H];   // Wz@xe+bz -> z after B1
__device__ float g_gr[NPAR * H];   // Wr@xe+br -> mem*r after B1
__device__ float g_gh[NPAR * H];   // Wh@xe+bh
__device__ float g_mem[NPAR * H];
__device__ float g_ph[NPAR * H];
__device__ float g_pmax[MAXB * H];

__device__ int g_lvl[NPAR];
__device__ int g_lstart[MAXL + 2];
__device__ int g_nlev;
__device__ int g_order[NPAR];

// flag-array barrier
__device__ volatile int g_arr[MAXGRID];
__device__ volatile int g_gen;

// ============================================================
__global__ void prep_kernel(const float* __restrict__ E_bu) {
    int idx = blockIdx.x * 256 + threadIdx.x;
    if (idx < VOCAB * H) {
        int v = idx / H, h = idx - v * H;
        g_Et[idx] = E_bu[h * VOCAB + v];
    }
    if (idx < MAXGRID) g_arr[idx] = 0;
    if (idx == 0) g_gen = 0;
}

// ============================================================
__global__ __launch_bounds__(128) void xe_kernel(const float* __restrict__ xw,
                                                 const int* __restrict__ xi) {
    __shared__ float sw[LW];
    __shared__ int si[LW];
    int n = blockIdx.x;
    int t = threadIdx.x;
    if (t < LW) { sw[t] = xw[n * LW + t]; si[t] = xi[n * LW + t]; }
    __syncthreads();
    float4 acc = make_float4(0.f, 0.f, 0.f, 0.f);
#pragma unroll 8
    for (int l = 0; l < LW; l++) {
        float w = sw[l];
        const float4 e = *(const float4*)&g_Et[si[l] * H + t * 4];
        acc.x += w * e.x; acc.y += w * e.y; acc.z += w * e.z; acc.w += w * e.w;
    }
    *(float4*)&g_xe[n * H + t * 4] = acc;
}

// ============================================================
// W-GEMMs (independent half of GRU), 128x128 tile
// ============================================================
#define BM 128
#define BN 128
#define BK 16
__global__ __launch_bounds__(256) void sgemm_nt(const float* __restrict__ B,
                                                const float* __restrict__ bias,
                                                int which) {
    const int M = NPAR;
    const float* A = g_xe + NLEAF * H;
    float* C = (which == 0) ? g_gz : (which == 1) ? g_gr : g_gh;
    __shared__ __align__(16) float As[BK][BM];
    __shared__ __align__(16) float Bs[BK][BN];
    int row0 = blockIdx.x * BM;
    int n0 = blockIdx.y * BN;
    int tid = threadIdx.x;
    int tr = tid >> 4, tc = tid & 15;

    float acc[8][8];
#pragma unroll
    for (int i = 0; i < 8; i++)
#pragma unroll
        for (int j = 0; j < 8; j++) acc[i][j] = 0.f;

    for (int k0 = 0; k0 < H; k0 += BK) {
#pragma unroll
        for (int i = 0; i < 2; i++) {
            int li = tid + i * 256;
            int m = li >> 2, kq = li & 3;
            int row = row0 + m;
            float4 f = make_float4(0.f, 0.f, 0.f, 0.f);
            if (row < M) f = *(const float4*)&A[row * H + k0 + kq * 4];
            As[kq * 4 + 0][m] = f.x; As[kq * 4 + 1][m] = f.y;
            As[kq * 4 + 2][m] = f.z; As[kq * 4 + 3][m] = f.w;
        }
#pragma unroll
        for (int i = 0; i < 2; i++) {
            int li = tid + i * 256;
            int nn = li >> 2, kq = li & 3;
            float4 f = *(const float4*)&B[(n0 + nn) * H + k0 + kq * 4];
            Bs[kq * 4 + 0][nn] = f.x; Bs[kq * 4 + 1][nn] = f.y;
            Bs[kq * 4 + 2][nn] = f.z; Bs[kq * 4 + 3][nn] = f.w;
        }
        __syncthreads();
#pragma unroll
        for (int kk = 0; kk < BK; kk++) {
            float ra[8], rb[8];
#pragma unroll
            for (int i = 0; i < 8; i++) ra[i] = As[kk][tr * 8 + i];
#pragma unroll
            for (int j = 0; j < 8; j++) rb[j] = Bs[kk][tc * 8 + j];
#pragma unroll
            for (int i = 0; i < 8; i++)
#pragma unroll
                for (int j = 0; j < 8; j++) acc[i][j] += ra[i] * rb[j];
        }
        __syncthreads();
    }
#pragma unroll
    for (int i = 0; i < 8; i++) {
        int row = row0 + tr * 8 + i;
        if (row >= M) continue;
#pragma unroll
        for (int j = 0; j < 8; j++) {
            int col = n0 + tc * 8 + j;
            C[row * H + col] = acc[i][j] + bias[col];
        }
    }
}

// ============================================================
// Levels + bucketing. Single block, 1024 threads.
// ============================================================
extern __shared__ int s_dyn[];
__global__ void levels_kernel(const int* __restrict__ tree) {
    volatile int* lvl = s_dyn;
    int tid = threadIdx.x;
    int nt = blockDim.x;
    __shared__ int changed;
    __shared__ int s_maxl;
    __shared__ int cnt[MAXL + 1];

    for (int p = tid; p < NPAR; p += nt) lvl[p] = 1;
    if (tid == 0) s_maxl = 1;
    __syncthreads();

    for (int it = 0; it < 4096; it++) {
        if (tid == 0) changed = 0;
        __syncthreads();
        int ch = 0;
        for (int p = tid; p < NPAR; p += nt) {
            int4 t4 = ((const int4*)tree)[p];
            int m = 1;
            int c, v;
            c = t4.x; if (c >= NLEAF) { v = lvl[c - NLEAF] + 1; if (v > m) m = v; }
            c = t4.y; if (c >= NLEAF) { v = lvl[c - NLEAF] + 1; if (v > m) m = v; }
            c = t4.z; if (c >= NLEAF) { v = lvl[c - NLEAF] + 1; if (v > m) m = v; }
            c = t4.w; if (c >= NLEAF) { v = lvl[c - NLEAF] + 1; if (v > m) m = v; }
            if (m > lvl[p]) { lvl[p] = m; ch = 1; }
        }
        if (ch) changed = 1;
        __syncthreads();
        if (!changed) break;
    }

    for (int i = tid; i <= MAXL; i += nt) cnt[i] = 0;
    __syncthreads();
    int mymax = 1;
    for (int p = tid; p < NPAR; p += nt) {
        int l = lvl[p]; if (l > MAXL) l = MAXL;
        atomicAdd(&cnt[l], 1);
        if (l > mymax) mymax = l;
    }
    atomicMax(&s_maxl, mymax);
    __syncthreads();
    if (tid == 0) {
        int acc = 0;
        for (int l = 0; l <= MAXL; l++) { g_lstart[l] = acc; acc += cnt[l]; }
        g_lstart[MAXL + 1] = acc;
        g_nlev = s_maxl;
    }
    __syncthreads();
    for (int i = tid; i <= MAXL; i += nt) cnt[i] = g_lstart[i];
    __syncthreads();
    for (int p = tid; p < NPAR; p += nt) {
        int l = lvl[p]; if (l > MAXL) l = MAXL;
        int pos = atomicAdd(&cnt[l], 1);
        g_order[pos] = p;
        g_lvl[p] = l;
    }
}

// ============================================================
// Persistent wavefront kernel
// ============================================================
struct alignas(16) ShA {
    float bufA[DEG][H];
    float bufB[DEG][H];
    float sc[HEADS][DEG][DEG];
    int cidx[DEG];
    int nc;
};
struct alignas(16) ShB {
    float As[16][32];
    float Bs[16][64];
    int pidx[32];
};

// flag-array sense barrier: no atomics, block0 scans in parallel
__device__ __forceinline__ void grid_sync2(int bid, int nb, int& cnt) {
    cnt++;
    __threadfence();
    __syncthreads();
    if (threadIdx.x == 0) g_arr[bid] = cnt;
    if (bid == 0) {
        for (int i = threadIdx.x; i < nb; i += blockDim.x) {
            while (g_arr[i] < cnt) __nanosleep(32);
        }
        __syncthreads();
        if (threadIdx.x == 0) { __threadfence(); g_gen = cnt; }
    } else {
        if (threadIdx.x == 0) {
            while (g_gen < cnt) __nanosleep(32);
            __threadfence();
        }
    }
    __syncthreads();
}

// 32 x 64 output tile, full K=512, direct-store epilogues (big levels).
template <int PHASE>
__device__ void gemm_tile(ShB* sb, int i0, int mtile, int jbase,
                          const float* __restrict__ Uz,
                          const float* __restrict__ Ur,
                          const float* __restrict__ Uh) {
    int tid = threadIdx.x;
    if (tid < 32) sb->pidx[tid] = g_order[i0 + ((tid < mtile) ? tid : 0)];
    __syncthreads();

    const float* Asrc = (PHASE == 1) ? g_mem : g_gr;
    const float* Bsrc;
    if (PHASE == 1) Bsrc = (jbase < H) ? (Uz + (size_t)jbase * H)
                                       : (Ur + (size_t)(jbase - H) * H);
    else            Bsrc = Uh + (size_t)jbase * H;

    float acc[2][4];
#pragma unroll
    for (int a = 0; a < 2; a++)
#pragma unroll
        for (int b = 0; b < 4; b++) acc[a][b] = 0.f;

    int tr = tid >> 4, tc = tid & 15;

    for (int k0 = 0; k0 < H; k0 += 16) {
        if (tid < 128) {
            int row = tid >> 2, kq = tid & 3;
            float4 f = *(const float4*)&Asrc[(size_t)sb->pidx[row] * H + k0 + kq * 4];
            sb->As[kq * 4 + 0][row] = f.x; sb->As[kq * 4 + 1][row] = f.y;
            sb->As[kq * 4 + 2][row] = f.z; sb->As[kq * 4 + 3][row] = f.w;
        }
        {
            int nn = tid >> 2, kq = tid & 3;
            float4 f = *(const float4*)&Bsrc[(size_t)nn * H + k0 + kq * 4];
            sb->Bs[kq * 4 + 0][nn] = f.x; sb->Bs[kq * 4 + 1][nn] = f.y;
            sb->Bs[kq * 4 + 2][nn] = f.z; sb->Bs[kq * 4 + 3][nn] = f.w;
        }
        __syncthreads();
#pragma unroll
        for (int kk = 0; kk < 16; kk++) {
            float2 ra = *(const float2*)&sb->As[kk][tr * 2];
            float4 rb = *(const float4*)&sb->Bs[kk][tc * 4];
            acc[0][0] += ra.x * rb.x; acc[0][1] += ra.x * rb.y;
            acc[0][2] += ra.x * rb.z; acc[0][3] += ra.x * rb.w;
            acc[1][0] += ra.y * rb.x; acc[1][1] += ra.y * rb.y;
            acc[1][2] += ra.y * rb.z; acc[1][3] += ra.y * rb.w;
        }
        __syncthreads();
    }

#pragma unroll
    for (int a = 0; a < 2; a++) {
        int i = tr * 2 + a;
        if (i >= mtile) continue;
        size_t pbase = (size_t)sb->pidx[i] * H;
#pragma unroll
        for (int b = 0; b < 4; b++) {
            int col = jbase + tc * 4 + b;
            float v = acc[a][b];
            if (PHASE == 1) {
                if (jbase < H) {
                    g_gz[pbase + col] = 1.0f / (1.0f + expf(-(v + g_gz[pbase + col])));
                } else {
                    int c2 = col - H;
                    float r = 1.0f / (1.0f + expf(-(v + g_gr[pbase + c2])));
                    g_gr[pbase + c2] = g_mem[pbase + c2] * r;
                }
            } else {
                float cc = tanhf(v + g_gh[pbase + col]);
                float z = g_gz[pbase + col];
                float m = g_mem[pbase + col];
                g_ph[pbase + col] = z * m + (1.0f - z) * cc;
            }
        }
    }
    __syncthreads();
}

__device__ __forceinline__ void do_attn(ShA* sa, int p, const int* __restrict__ tree) {
    int tid = threadIdx.x;
    if (tid == 0) {
        int nc = 0;
#pragma unroll
        for (int j = 0; j < DEG; j++) {
            int c = tree[p * DEG + j];
            if (c > -1) sa->cidx[nc++] = c;
        }
        sa->nc = nc;
    }
    __syncthreads();
    int nc = sa->nc;

    for (int i = 0; i < nc; i++) {
        int c = sa->cidx[i];
        const float* src = (c < NLEAF) ? &g_xe[(size_t)c * H]
                                       : &g_ph[(size_t)(c - NLEAF) * H];
        if (tid < 128) ((float4*)sa->bufA[i])[tid] = ((const float4*)src)[tid];
    }
    __syncthreads();

    float (*cur)[H] = sa->bufA;
    float (*nxt)[H] = sa->bufB;

    for (int layer = 0; layer < NLAYER; layer++) {
        int tot = HEADS * nc * nc;
        for (int t = tid; t < tot; t += 256) {
            int hd = t / (nc * nc);
            int r2 = t - hd * nc * nc;
            int q = r2 / nc, k = r2 - q * nc;
            const float* qp = &cur[q][hd * DK];
            const float* kp = &cur[k][hd * DK];
            float s = 0.f;
#pragma unroll 16
            for (int d = 0; d < DK; d++) s += qp[d] * kp[d];
            sa->sc[hd][q][k] = s * 0.125f;
        }
        __syncthreads();
        for (int t = tid; t < HEADS * nc; t += 256) {
            int hd = t / nc, q = t - hd * nc;
            float m = -1e30f;
            for (int k = 0; k < nc; k++) m = fmaxf(m, sa->sc[hd][q][k]);
            float ssum = 0.f;
            for (int k = 0; k < nc; k++) {
                float e = expf(sa->sc[hd][q][k] - m);
                ssum += e;
                sa->sc[hd][q][k] = e;
            }
            float inv = 1.0f / ssum;
            for (int k = 0; k < nc; k++) sa->sc[hd][q][k] *= inv;
        }
        __syncthreads();
        for (int c = tid; c < H; c += 256) {
            int hd = c >> 6;
            for (int q = 0; q < nc; q++) {
                float o = 0.f;
                for (int k = 0; k < nc; k++) o += sa->sc[hd][q][k] * cur[k][c];
                nxt[q][c] = o;
            }
        }
        __syncthreads();
        float (*tmp)[H] = cur; cur = nxt; nxt = tmp;
    }
    float invn = 1.0f / (float)nc;
    for (int c = tid; c < H; c += 256) {
        float s = 0.f;
        for (int q = 0; q < nc; q++) s += cur[q][c];
        g_mem[(size_t)p * H + c] = s * invn;
    }
    __syncthreads();
}

__global__ __launch_bounds__(256) void wave_kernel(const int* __restrict__ tree,
                                                   const float* __restrict__ Uz,
                                                   const float* __restrict__ Ur,
                                                   const float* __restrict__ Uh,
                                                   int small_thresh) {
    __shared__ union alignas(16) { ShA a; ShB b; } sh;
    __shared__ __align__(16) float uRows[RPB_MAX][H];   // this block's resident U rows
    int tid = threadIdx.x;
    int bid = blockIdx.x;
    int nb = gridDim.x;
    int wid = tid >> 5, lane = tid & 31;
    int nlev = g_nlev;
    int cnt = 0;

    // rows per block (matches host formula), this block's row range
    int rpb = (NROWS + nb - 1) / nb;
    if (rpb > RPB_MAX) rpb = RPB_MAX;  // host disables GEMV if insufficient
    int myrow0 = bid * rpb;
    int mynrows = NROWS - myrow0;
    if (mynrows < 0) mynrows = 0;
    if (mynrows > rpb) mynrows = rpb;

    // stage this block's U rows into smem (float4, 128 threads per row)
    for (int rr = 0; rr < mynrows; rr++) {
        int R = myrow0 + rr;
        const float* src = (R < H) ? &Uz[(size_t)R * H]
                         : (R < 2 * H) ? &Ur[(size_t)(R - H) * H]
                         : &Uh[(size_t)(R - 2 * H) * H];
        if (tid < 128) ((float4*)uRows[rr])[tid] = ((const float4*)src)[tid];
    }
    __syncthreads();

    for (int l = 1; l <= nlev; l++) {
        int ls = g_lstart[l];
        int le = g_lstart[l + 1];
        int Nl = le - ls;

        // ---- Phase A: attention + memory ----
        for (int ii = ls + bid; ii < le; ii += nb) {
            do_attn(&sh.a, g_order[ii], tree);
        }
        grid_sync2(bid, nb, cnt);

        if (Nl <= small_thresh) {
            // ---- small-level GEMV path (weight-stationary) ----
            // B1: z/r rows (R < 1024)
            {
                int nzr = 0;
                int zr_rr[RPB_MAX];
                for (int rr = 0; rr < mynrows; rr++)
                    if (myrow0 + rr < 2 * H) zr_rr[nzr++] = rr;
                int ntask = nzr * Nl;
                for (int t = wid; t < ntask; t += 8) {
                    int ri = t / Nl;
                    int pi = t - ri * Nl;
                    int rr = zr_rr[ri];
                    int R = myrow0 + rr;
                    int p = g_order[ls + pi];
                    const float* mem = &g_mem[(size_t)p * H];
                    float s = 0.f;
#pragma unroll
                    for (int j = 0; j < 4; j++) {
                        int k = 4 * (lane + 32 * j);
                        float4 u = *(const float4*)&uRows[rr][k];
                        float4 m = *(const float4*)&mem[k];
                        s += u.x * m.x + u.y * m.y + u.z * m.z + u.w * m.w;
                    }
#pragma unroll
                    for (int o = 16; o > 0; o >>= 1) s += __shfl_down_sync(0xffffffffu, s, o);
                    if (lane == 0) {
                        if (R < H) {
                            size_t a = (size_t)p * H + R;
                            g_gz[a] = 1.0f / (1.0f + expf(-(s + g_gz[a])));
                        } else {
                            int r2 = R - H;
                            size_t a = (size_t)p * H + r2;
                            float r = 1.0f / (1.0f + expf(-(s + g_gr[a])));
                            g_gr[a] = mem[r2] * r;
                        }
                    }
                }
            }
            grid_sync2(bid, nb, cnt);

            // B2: c rows (R >= 1024), A-vector = g_gr (= mem*r)
            {
                int ncr = 0;
                int c_rr[RPB_MAX];
                for (int rr = 0; rr < mynrows; rr++)
                    if (myrow0 + rr >= 2 * H) c_rr[ncr++] = rr;
                int ntask = ncr * Nl;
                for (int t = wid; t < ntask; t += 8) {
                    int ri = t / Nl;
                    int pi = t - ri * Nl;
                    int rr = c_rr[ri];
                    int row = myrow0 + rr - 2 * H;
                    int p = g_order[ls + pi];
                    const float* av = &g_gr[(size_t)p * H];
                    float s = 0.f;
#pragma unroll
                    for (int j = 0; j < 4; j++) {
                        int k = 4 * (lane + 32 * j);
                        float4 u = *(const float4*)&uRows[rr][k];
                        float4 m = *(const float4*)&av[k];
                        s += u.x * m.x + u.y * m.y + u.z * m.z + u.w * m.w;
                    }
#pragma unroll
                    for (int o = 16; o > 0; o >>= 1) s += __shfl_down_sync(0xffffffffu, s, o);
                    if (lane == 0) {
                        size_t a = (size_t)p * H + row;
                        float cc = tanhf(s + g_gh[a]);
                        float z = g_gz[a];
                        float m = g_mem[a];
                        g_ph[a] = z * m + (1.0f - z) * cc;
                    }
                }
            }
            grid_sync2(bid, nb, cnt);
        } else {
            // ---- big-level tile path ----
            int pt32 = (Nl + 31) >> 5;
            int ntiles = pt32 * 16;
            for (int t = bid; t < ntiles; t += nb) {
                int pt = t >> 4;
                int jbase = (t & 15) * 64;
                int i0 = ls + pt * 32;
                int mtile = Nl - pt * 32; if (mtile > 32) mtile = 32;
                gemm_tile<1>(&sh.b, i0, mtile, jbase, Uz, Ur, Uh);
            }
            grid_sync2(bid, nb, cnt);

            ntiles = pt32 * 8;
            for (int t = bid; t < ntiles; t += nb) {
                int pt = t >> 3;
                int jbase = (t & 7) * 64;
                int i0 = ls + pt * 32;
                int mtile = Nl - pt * 32; if (mtile > 32) mtile = 32;
                gemm_tile<2>(&sh.b, i0, mtile, jbase, Uz, Ur, Uh);
            }
            grid_sync2(bid, nb, cnt);
        }
    }
}

// ============================================================
__global__ void maxk_kernel() {
    int b = blockIdx.x;
    int rows_per = (NPAR + MAXB - 1) / MAXB;
    int r0 = b * rows_per;
    int r1 = min(NPAR, r0 + rows_per);
    for (int c = threadIdx.x; c < H; c += 256) {
        float m = -1e30f;
        for (int r = r0; r < r1; r++) m = fmaxf(m, g_ph[r * H + c]);
        g_pmax[b * H + c] = m;
    }
}

__global__ __launch_bounds__(512) void final_kernel(const float* __restrict__ Wout,
                                                    const float* __restrict__ bout,
                                                    float* __restrict__ out) {
    __shared__ float fin[H];
    __shared__ float logits[NCLASS];
    int tid = threadIdx.x;
    if (tid < H) {
        float m = -1e30f;
        for (int b = 0; b < MAXB; b++) m = fmaxf(m, g_pmax[b * H + tid]);
        fin[tid] = m;
    }
    __syncthreads();
    if (tid < NCLASS * 32) {
        int cls = tid >> 5, lane = tid & 31;
        float s = 0.f;
        for (int h = lane; h < H; h += 32) s += Wout[cls * H + h] * fin[h];
#pragma unroll
        for (int o = 16; o > 0; o >>= 1) s += __shfl_down_sync(0xffffffffu, s, o);
        if (lane == 0) logits[cls] = s + bout[cls];
    }
    __syncthreads();
    if (tid == 0) {
        float m = fmaxf(fmaxf(logits[0], logits[1]), fmaxf(logits[2], logits[3]));
        float e0 = expf(logits[0] - m), e1 = expf(logits[1] - m);
        float e2 = expf(logits[2] - m), e3 = expf(logits[3] - m);
        float inv = 1.0f / (e0 + e1 + e2 + e3);
        out[0] = e0 * inv; out[1] = e1 * inv; out[2] = e2 * inv; out[3] = e3 * inv;
    }
}

// ============================================================
extern "C" void kernel_launch(void* const* d_in, const int* in_sizes, int n_in,
                              void* d_out, int out_size) {
    const float* xw   = (const float*)d_in[0];
    const int*   xi   = (const int*)d_in[1];
    const int*   tree = (const int*)d_in[2];
    const float* E    = (const float*)d_in[3];
    const float* Wz   = (const float*)d_in[4];
    const float* Uz   = (const float*)d_in[5];
    const float* bz   = (const float*)d_in[6];
    const float* Wr   = (const float*)d_in[7];
    const float* Ur   = (const float*)d_in[8];
    const float* br   = (const float*)d_in[9];
    const float* Wh   = (const float*)d_in[10];
    const float* Uh   = (const float*)d_in[11];
    const float* bh   = (const float*)d_in[12];
    const float* Wout = (const float*)d_in[13];
    const float* bout = (const float*)d_in[14];

    cudaFuncSetAttribute(levels_kernel,
                         cudaFuncAttributeMaxDynamicSharedMemorySize, NPAR * 4 + 1024);
    int perSM = 0;
    cudaOccupancyMaxActiveBlocksPerMultiprocessor(&perSM, wave_kernel, 256, 0);
    if (perSM < 1) perSM = 1;
    if (perSM > 4) perSM = 4;
    int nsm = 0;
    cudaDeviceGetAttribute(&nsm, cudaDevAttrMultiProcessorCount, 0);
    if (nsm <= 0) nsm = 148;
    int grid = perSM * nsm;
    if (grid > MAXGRID) grid = MAXGRID;

    // GEMV path only if every row fits in some block's cache
    int rpb = (NROWS + grid - 1) / grid;
    int small_thresh = (rpb <= RPB_MAX) ? 96 : 0;

    prep_kernel<<<(VOCAB * H + 255) / 256, 256>>>(E);
    xe_kernel<<<NTOT, 128>>>(xw, xi);

    dim3 gg((NPAR + BM - 1) / BM, H / BN);
    sgemm_nt<<<gg, 256>>>(Wz, bz, 0);
    sgemm_nt<<<gg, 256>>>(Wr, br, 1);
    sgemm_nt<<<gg, 256>>>(Wh, bh, 2);

    levels_kernel<<<1, 1024, NPAR * 4>>>(tree);
    wave_kernel<<<grid, 256>>>(tree, Uz, Ur, Uh, small_thresh);

    maxk_kernel<<<MAXB, 256>>>();
    final_kernel<<<1, 512>>>(Wout, bout, (float*)d_out);
    (void)in_sizes; (void)n_in; (void)out_size;
}

// round 9
// speedup vs baseline: 1.3762x; 1.1153x over previous
#include <cuda_runtime.h>
#include <math.h>

#define H 512
#define HEADS 8
#define DK 64
#define NCLASS 4
#define VOCAB 5000
#define LW 32
#define NLEAF 20000
#define NPAR 20000
#define NTOT (NLEAF + NPAR)
#define DEG 4
#define NLAYER 5
#define MAXB 64
#define MAXL 512
#define MAXGRID 1024
#define NROWS 1536           // 512 Uz + 512 Ur + 512 Uh
#define RPB_MAX 8            // max U rows cached per block

// ---- static device scratch ----
__device__ float g_Et[VOCAB * H];
__device__ float g_xe[NTOT * H];
__device__ float g_gz[NPAR * H];   // Wz@xe+bz -> z after B1
__device__ float g_gr[NPAR * H];   // Wr@xe+br -> mem*r after B1
__device__ float g_gh[NPAR * H];   // Wh@xe+bh
__device__ float g_mem[NPAR * H];
__device__ float g_ph[NPAR * H];
__device__ float g_pmax[MAXB * H];

__device__ int g_lvl[NPAR];
__device__ int g_lstart[MAXL + 2];
__device__ int g_nlev;
__device__ int g_order[NPAR];

// flag-array barrier
__device__ volatile int g_arr[MAXGRID];
__device__ volatile int g_gen;

// ============================================================
__global__ void prep_kernel(const float* __restrict__ E_bu) {
    int idx = blockIdx.x * 256 + threadIdx.x;
    if (idx < VOCAB * H) {
        int v = idx / H, h = idx - v * H;
        g_Et[idx] = E_bu[h * VOCAB + v];
    }
    if (idx < MAXGRID) g_arr[idx] = 0;
    if (idx == 0) g_gen = 0;
}

// ============================================================
__global__ __launch_bounds__(128) void xe_kernel(const float* __restrict__ xw,
                                                 const int* __restrict__ xi) {
    __shared__ float sw[LW];
    __shared__ int si[LW];
    int n = blockIdx.x;
    int t = threadIdx.x;
    if (t < LW) { sw[t] = xw[n * LW + t]; si[t] = xi[n * LW + t]; }
    __syncthreads();
    float4 acc = make_float4(0.f, 0.f, 0.f, 0.f);
#pragma unroll 8
    for (int l = 0; l < LW; l++) {
        float w = sw[l];
        const float4 e = *(const float4*)&g_Et[si[l] * H + t * 4];
        acc.x += w * e.x; acc.y += w * e.y; acc.z += w * e.z; acc.w += w * e.w;
    }
    *(float4*)&g_xe[n * H + t * 4] = acc;
}

// ============================================================
// W-GEMMs (independent half of GRU), 128x128 tile
// ============================================================
#define BM 128
#define BN 128
#define BK 16
__global__ __launch_bounds__(256) void sgemm_nt(const float* __restrict__ B,
                                                const float* __restrict__ bias,
                                                int which) {
    const int M = NPAR;
    const float* A = g_xe + NLEAF * H;
    float* C = (which == 0) ? g_gz : (which == 1) ? g_gr : g_gh;
    __shared__ __align__(16) float As[BK][BM];
    __shared__ __align__(16) float Bs[BK][BN];
    int row0 = blockIdx.x * BM;
    int n0 = blockIdx.y * BN;
    int tid = threadIdx.x;
    int tr = tid >> 4, tc = tid & 15;

    float acc[8][8];
#pragma unroll
    for (int i = 0; i < 8; i++)
#pragma unroll
        for (int j = 0; j < 8; j++) acc[i][j] = 0.f;

    for (int k0 = 0; k0 < H; k0 += BK) {
#pragma unroll
        for (int i = 0; i < 2; i++) {
            int li = tid + i * 256;
            int m = li >> 2, kq = li & 3;
            int row = row0 + m;
            float4 f = make_float4(0.f, 0.f, 0.f, 0.f);
            if (row < M) f = *(const float4*)&A[row * H + k0 + kq * 4];
            As[kq * 4 + 0][m] = f.x; As[kq * 4 + 1][m] = f.y;
            As[kq * 4 + 2][m] = f.z; As[kq * 4 + 3][m] = f.w;
        }
#pragma unroll
        for (int i = 0; i < 2; i++) {
            int li = tid + i * 256;
            int nn = li >> 2, kq = li & 3;
            float4 f = *(const float4*)&B[(n0 + nn) * H + k0 + kq * 4];
            Bs[kq * 4 + 0][nn] = f.x; Bs[kq * 4 + 1][nn] = f.y;
            Bs[kq * 4 + 2][nn] = f.z; Bs[kq * 4 + 3][nn] = f.w;
        }
        __syncthreads();
#pragma unroll
        for (int kk = 0; kk < BK; kk++) {
            float ra[8], rb[8];
#pragma unroll
            for (int i = 0; i < 8; i++) ra[i] = As[kk][tr * 8 + i];
#pragma unroll
            for (int j = 0; j < 8; j++) rb[j] = Bs[kk][tc * 8 + j];
#pragma unroll
            for (int i = 0; i < 8; i++)
#pragma unroll
                for (int j = 0; j < 8; j++) acc[i][j] += ra[i] * rb[j];
        }
        __syncthreads();
    }
#pragma unroll
    for (int i = 0; i < 8; i++) {
        int row = row0 + tr * 8 + i;
        if (row >= M) continue;
#pragma unroll
        for (int j = 0; j < 8; j++) {
            int col = n0 + tc * 8 + j;
            C[row * H + col] = acc[i][j] + bias[col];
        }
    }
}

// ============================================================
// Levels + bucketing. Single block, 1024 threads.
// ============================================================
extern __shared__ int s_dyn[];
__global__ void levels_kernel(const int* __restrict__ tree) {
    volatile int* lvl = s_dyn;
    int tid = threadIdx.x;
    int nt = blockDim.x;
    __shared__ int changed;
    __shared__ int s_maxl;
    __shared__ int cnt[MAXL + 1];

    for (int p = tid; p < NPAR; p += nt) lvl[p] = 1;
    if (tid == 0) s_maxl = 1;
    __syncthreads();

    for (int it = 0; it < 4096; it++) {
        if (tid == 0) changed = 0;
        __syncthreads();
        int ch = 0;
        for (int p = tid; p < NPAR; p += nt) {
            int4 t4 = ((const int4*)tree)[p];
            int m = 1;
            int c, v;
            c = t4.x; if (c >= NLEAF) { v = lvl[c - NLEAF] + 1; if (v > m) m = v; }
            c = t4.y; if (c >= NLEAF) { v = lvl[c - NLEAF] + 1; if (v > m) m = v; }
            c = t4.z; if (c >= NLEAF) { v = lvl[c - NLEAF] + 1; if (v > m) m = v; }
            c = t4.w; if (c >= NLEAF) { v = lvl[c - NLEAF] + 1; if (v > m) m = v; }
            if (m > lvl[p]) { lvl[p] = m; ch = 1; }
        }
        if (ch) changed = 1;
        __syncthreads();
        if (!changed) break;
    }

    for (int i = tid; i <= MAXL; i += nt) cnt[i] = 0;
    __syncthreads();
    int mymax = 1;
    for (int p = tid; p < NPAR; p += nt) {
        int l = lvl[p]; if (l > MAXL) l = MAXL;
        atomicAdd(&cnt[l], 1);
        if (l > mymax) mymax = l;
    }
    atomicMax(&s_maxl, mymax);
    __syncthreads();
    if (tid == 0) {
        int acc = 0;
        for (int l = 0; l <= MAXL; l++) { g_lstart[l] = acc; acc += cnt[l]; }
        g_lstart[MAXL + 1] = acc;
        g_nlev = s_maxl;
    }
    __syncthreads();
    for (int i = tid; i <= MAXL; i += nt) cnt[i] = g_lstart[i];
    __syncthreads();
    for (int p = tid; p < NPAR; p += nt) {
        int l = lvl[p]; if (l > MAXL) l = MAXL;
        int pos = atomicAdd(&cnt[l], 1);
        g_order[pos] = p;
        g_lvl[p] = l;
    }
}

// ============================================================
// Persistent wavefront kernel
// ============================================================
struct alignas(16) ShB {
    float As[16][32];
    float Bs[16][64];
    int pidx[32];
};

// flag-array sense barrier: no atomics, block0 scans in parallel
__device__ __forceinline__ void grid_sync2(int bid, int nb, int& cnt) {
    cnt++;
    __threadfence();
    __syncthreads();
    if (threadIdx.x == 0) g_arr[bid] = cnt;
    if (bid == 0) {
        for (int i = threadIdx.x; i < nb; i += blockDim.x) {
            while (g_arr[i] < cnt) __nanosleep(32);
        }
        __syncthreads();
        if (threadIdx.x == 0) { __threadfence(); g_gen = cnt; }
    } else {
        if (threadIdx.x == 0) {
            while (g_gen < cnt) __nanosleep(32);
            __threadfence();
        }
    }
    __syncthreads();
}

// 32 x 64 output tile, full K=512, direct-store epilogues (big levels).
template <int PHASE>
__device__ void gemm_tile(ShB* sb, int i0, int mtile, int jbase,
                          const float* __restrict__ Uz,
                          const float* __restrict__ Ur,
                          const float* __restrict__ Uh) {
    int tid = threadIdx.x;
    if (tid < 32) sb->pidx[tid] = g_order[i0 + ((tid < mtile) ? tid : 0)];
    __syncthreads();

    const float* Asrc = (PHASE == 1) ? g_mem : g_gr;
    const float* Bsrc;
    if (PHASE == 1) Bsrc = (jbase < H) ? (Uz + (size_t)jbase * H)
                                       : (Ur + (size_t)(jbase - H) * H);
    else            Bsrc = Uh + (size_t)jbase * H;

    float acc[2][4];
#pragma unroll
    for (int a = 0; a < 2; a++)
#pragma unroll
        for (int b = 0; b < 4; b++) acc[a][b] = 0.f;

    int tr = tid >> 4, tc = tid & 15;

    for (int k0 = 0; k0 < H; k0 += 16) {
        if (tid < 128) {
            int row = tid >> 2, kq = tid & 3;
            float4 f = *(const float4*)&Asrc[(size_t)sb->pidx[row] * H + k0 + kq * 4];
            sb->As[kq * 4 + 0][row] = f.x; sb->As[kq * 4 + 1][row] = f.y;
            sb->As[kq * 4 + 2][row] = f.z; sb->As[kq * 4 + 3][row] = f.w;
        }
        {
            int nn = tid >> 2, kq = tid & 3;
            float4 f = *(const float4*)&Bsrc[(size_t)nn * H + k0 + kq * 4];
            sb->Bs[kq * 4 + 0][nn] = f.x; sb->Bs[kq * 4 + 1][nn] = f.y;
            sb->Bs[kq * 4 + 2][nn] = f.z; sb->Bs[kq * 4 + 3][nn] = f.w;
        }
        __syncthreads();
#pragma unroll
        for (int kk = 0; kk < 16; kk++) {
            float2 ra = *(const float2*)&sb->As[kk][tr * 2];
            float4 rb = *(const float4*)&sb->Bs[kk][tc * 4];
            acc[0][0] += ra.x * rb.x; acc[0][1] += ra.x * rb.y;
            acc[0][2] += ra.x * rb.z; acc[0][3] += ra.x * rb.w;
            acc[1][0] += ra.y * rb.x; acc[1][1] += ra.y * rb.y;
            acc[1][2] += ra.y * rb.z; acc[1][3] += ra.y * rb.w;
        }
        __syncthreads();
    }

#pragma unroll
    for (int a = 0; a < 2; a++) {
        int i = tr * 2 + a;
        if (i >= mtile) continue;
        size_t pbase = (size_t)sb->pidx[i] * H;
#pragma unroll
        for (int b = 0; b < 4; b++) {
            int col = jbase + tc * 4 + b;
            float v = acc[a][b];
            if (PHASE == 1) {
                if (jbase < H) {
                    g_gz[pbase + col] = 1.0f / (1.0f + expf(-(v + g_gz[pbase + col])));
                } else {
                    int c2 = col - H;
                    float r = 1.0f / (1.0f + expf(-(v + g_gr[pbase + c2])));
                    g_gr[pbase + c2] = g_mem[pbase + c2] * r;
                }
            } else {
                float cc = tanhf(v + g_gh[pbase + col]);
                float z = g_gz[pbase + col];
                float m = g_mem[pbase + col];
                g_ph[pbase + col] = z * m + (1.0f - z) * cc;
            }
        }
    }
    __syncthreads();
}

// ============================================================
// Warp-level attention: one warp handles (parent p, head hd).
// All state in registers; no shared memory, no block syncs.
// ============================================================
__device__ __forceinline__ void warp_attn(int p, int hd, int lane,
                                          const int* __restrict__ tree) {
    // gather children (uniform across warp)
    int4 t4 = ((const int4*)tree)[p];
    int carr[DEG] = {t4.x, t4.y, t4.z, t4.w};
    int cidx[DEG];
    int nc = 0;
#pragma unroll
    for (int j = 0; j < DEG; j++) {
        int c = carr[j];
        if (c > -1) cidx[nc++] = c;
    }

    // load cur[q] = h[child q][hd*64 + lane*2 .. +1]; pad rows = 0
    float2 cur[DEG];
#pragma unroll
    for (int q = 0; q < DEG; q++) {
        if (q < nc) {
            int c = cidx[q];
            const float* src = (c < NLEAF) ? &g_xe[(size_t)c * H]
                                           : &g_ph[(size_t)(c - NLEAF) * H];
            cur[q] = *(const float2*)&src[hd * DK + lane * 2];
        } else {
            cur[q] = make_float2(0.f, 0.f);
        }
    }

#pragma unroll
    for (int layer = 0; layer < NLAYER; layer++) {
        // scores (symmetric): butterfly-sum over the warp
        float sc[DEG][DEG];
#pragma unroll
        for (int q = 0; q < DEG; q++) {
#pragma unroll
            for (int k = 0; k <= q; k++) {
                float s = cur[q].x * cur[k].x + cur[q].y * cur[k].y;
#pragma unroll
                for (int o = 16; o > 0; o >>= 1)
                    s += __shfl_xor_sync(0xffffffffu, s, o);
                s *= 0.125f;
                sc[q][k] = s;
                sc[k][q] = s;
            }
        }
        // softmax over valid keys + AV (all lanes redundant)
        float2 nxt[DEG];
#pragma unroll
        for (int q = 0; q < DEG; q++) {
            float m = -1e30f;
#pragma unroll
            for (int k = 0; k < DEG; k++) {
                float v = (k < nc) ? sc[q][k] : -1e30f;
                m = fmaxf(m, v);
            }
            float pk[DEG];
            float ssum = 0.f;
#pragma unroll
            for (int k = 0; k < DEG; k++) {
                float e = (k < nc) ? __expf(sc[q][k] - m) : 0.f;
                pk[k] = e;
                ssum += e;
            }
            float inv = 1.0f / ssum;
            float2 o = make_float2(0.f, 0.f);
#pragma unroll
            for (int k = 0; k < DEG; k++) {
                float w = pk[k] * inv;
                o.x += w * cur[k].x;
                o.y += w * cur[k].y;
            }
            nxt[q] = o;
        }
#pragma unroll
        for (int q = 0; q < DEG; q++) cur[q] = nxt[q];
    }

    // memory slice = mean over valid rows
    float2 mm = make_float2(0.f, 0.f);
#pragma unroll
    for (int q = 0; q < DEG; q++) {
        if (q < nc) { mm.x += cur[q].x; mm.y += cur[q].y; }
    }
    float invn = 1.0f / (float)nc;
    mm.x *= invn; mm.y *= invn;
    *(float2*)&g_mem[(size_t)p * H + hd * DK + lane * 2] = mm;
}

__global__ __launch_bounds__(256) void wave_kernel(const int* __restrict__ tree,
                                                   const float* __restrict__ Uz,
                                                   const float* __restrict__ Ur,
                                                   const float* __restrict__ Uh,
                                                   int small_thresh) {
    __shared__ alignas(16) ShB shb;
    __shared__ __align__(16) float uRows[RPB_MAX][H];   // this block's resident U rows
    int tid = threadIdx.x;
    int bid = blockIdx.x;
    int nb = gridDim.x;
    int wid = tid >> 5, lane = tid & 31;
    int nlev = g_nlev;
    int cnt = 0;

    // rows per block (matches host formula), this block's row range
    int rpb = (NROWS + nb - 1) / nb;
    if (rpb > RPB_MAX) rpb = RPB_MAX;  // host disables GEMV if insufficient
    int myrow0 = bid * rpb;
    int mynrows = NROWS - myrow0;
    if (mynrows < 0) mynrows = 0;
    if (mynrows > rpb) mynrows = rpb;

    // stage this block's U rows into smem (float4, 128 threads per row)
    for (int rr = 0; rr < mynrows; rr++) {
        int R = myrow0 + rr;
        const float* src = (R < H) ? &Uz[(size_t)R * H]
                         : (R < 2 * H) ? &Ur[(size_t)(R - H) * H]
                         : &Uh[(size_t)(R - 2 * H) * H];
        if (tid < 128) ((float4*)uRows[rr])[tid] = ((const float4*)src)[tid];
    }
    __syncthreads();

    int gw = bid * 8 + wid;     // global warp id
    int ngw = nb * 8;

    for (int l = 1; l <= nlev; l++) {
        int ls = g_lstart[l];
        int le = g_lstart[l + 1];
        int Nl = le - ls;

        // ---- Phase A: warp-parallel attention ----
        {
            int ntask = Nl * HEADS;
            for (int t = gw; t < ntask; t += ngw) {
                int pi = t >> 3;
                int hd = t & 7;
                warp_attn(g_order[ls + pi], hd, lane, tree);
            }
        }
        grid_sync2(bid, nb, cnt);

        if (Nl <= small_thresh) {
            // ---- small-level GEMV path (weight-stationary) ----
            // B1: z/r rows (R < 1024)
            {
                int nzr = 0;
                int zr_rr[RPB_MAX];
                for (int rr = 0; rr < mynrows; rr++)
                    if (myrow0 + rr < 2 * H) zr_rr[nzr++] = rr;
                int ntask = nzr * Nl;
                for (int t = wid; t < ntask; t += 8) {
                    int ri = t / Nl;
                    int pi = t - ri * Nl;
                    int rr = zr_rr[ri];
                    int R = myrow0 + rr;
                    int p = g_order[ls + pi];
                    const float* mem = &g_mem[(size_t)p * H];
                    float s = 0.f;
#pragma unroll
                    for (int j = 0; j < 4; j++) {
                        int k = 4 * (lane + 32 * j);
                        float4 u = *(const float4*)&uRows[rr][k];
                        float4 m = *(const float4*)&mem[k];
                        s += u.x * m.x + u.y * m.y + u.z * m.z + u.w * m.w;
                    }
#pragma unroll
                    for (int o = 16; o > 0; o >>= 1) s += __shfl_down_sync(0xffffffffu, s, o);
                    if (lane == 0) {
                        if (R < H) {
                            size_t a = (size_t)p * H + R;
                            g_gz[a] = 1.0f / (1.0f + expf(-(s + g_gz[a])));
                        } else {
                            int r2 = R - H;
                            size_t a = (size_t)p * H + r2;
                            float r = 1.0f / (1.0f + expf(-(s + g_gr[a])));
                            g_gr[a] = mem[r2] * r;
                        }
                    }
                }
            }
            grid_sync2(bid, nb, cnt);

            // B2: c rows (R >= 1024), A-vector = g_gr (= mem*r)
            {
                int ncr = 0;
                int c_rr[RPB_MAX];
                for (int rr = 0; rr < mynrows; rr++)
                    if (myrow0 + rr >= 2 * H) c_rr[ncr++] = rr;
                int ntask = ncr * Nl;
                for (int t = wid; t < ntask; t += 8) {
                    int ri = t / Nl;
                    int pi = t - ri * Nl;
                    int rr = c_rr[ri];
                    int row = myrow0 + rr - 2 * H;
                    int p = g_order[ls + pi];
                    const float* av = &g_gr[(size_t)p * H];
                    float s = 0.f;
#pragma unroll
                    for (int j = 0; j < 4; j++) {
                        int k = 4 * (lane + 32 * j);
                        float4 u = *(const float4*)&uRows[rr][k];
                        float4 m = *(const float4*)&av[k];
                        s += u.x * m.x + u.y * m.y + u.z * m.z + u.w * m.w;
                    }
#pragma unroll
                    for (int o = 16; o > 0; o >>= 1) s += __shfl_down_sync(0xffffffffu, s, o);
                    if (lane == 0) {
                        size_t a = (size_t)p * H + row;
                        float cc = tanhf(s + g_gh[a]);
                        float z = g_gz[a];
                        float m = g_mem[a];
                        g_ph[a] = z * m + (1.0f - z) * cc;
                    }
                }
            }
            grid_sync2(bid, nb, cnt);
        } else {
            // ---- big-level tile path ----
            int pt32 = (Nl + 31) >> 5;
            int ntiles = pt32 * 16;
            for (int t = bid; t < ntiles; t += nb) {
                int pt = t >> 4;
                int jbase = (t & 15) * 64;
                int i0 = ls + pt * 32;
                int mtile = Nl - pt * 32; if (mtile > 32) mtile = 32;
                gemm_tile<1>(&shb, i0, mtile, jbase, Uz, Ur, Uh);
            }
            grid_sync2(bid, nb, cnt);

            ntiles = pt32 * 8;
            for (int t = bid; t < ntiles; t += nb) {
                int pt = t >> 3;
                int jbase = (t & 7) * 64;
                int i0 = ls + pt * 32;
                int mtile = Nl - pt * 32; if (mtile > 32) mtile = 32;
                gemm_tile<2>(&shb, i0, mtile, jbase, Uz, Ur, Uh);
            }
            grid_sync2(bid, nb, cnt);
        }
    }
}

// ============================================================
__global__ void maxk_kernel() {
    int b = blockIdx.x;
    int rows_per = (NPAR + MAXB - 1) / MAXB;
    int r0 = b * rows_per;
    int r1 = min(NPAR, r0 + rows_per);
    for (int c = threadIdx.x; c < H; c += 256) {
        float m = -1e30f;
        for (int r = r0; r < r1; r++) m = fmaxf(m, g_ph[r * H + c]);
        g_pmax[b * H + c] = m;
    }
}

__global__ __launch_bounds__(512) void final_kernel(const float* __restrict__ Wout,
                                                    const float* __restrict__ bout,
                                                    float* __restrict__ out) {
    __shared__ float fin[H];
    __shared__ float logits[NCLASS];
    int tid = threadIdx.x;
    if (tid < H) {
        float m = -1e30f;
        for (int b = 0; b < MAXB; b++) m = fmaxf(m, g_pmax[b * H + tid]);
        fin[tid] = m;
    }
    __syncthreads();
    if (tid < NCLASS * 32) {
        int cls = tid >> 5, lane = tid & 31;
        float s = 0.f;
        for (int h = lane; h < H; h += 32) s += Wout[cls * H + h] * fin[h];
#pragma unroll
        for (int o = 16; o > 0; o >>= 1) s += __shfl_down_sync(0xffffffffu, s, o);
        if (lane == 0) logits[cls] = s + bout[cls];
    }
    __syncthreads();
    if (tid == 0) {
        float m = fmaxf(fmaxf(logits[0], logits[1]), fmaxf(logits[2], logits[3]));
        float e0 = expf(logits[0] - m), e1 = expf(logits[1] - m);
        float e2 = expf(logits[2] - m), e3 = expf(logits[3] - m);
        float inv = 1.0f / (e0 + e1 + e2 + e3);
        out[0] = e0 * inv; out[1] = e1 * inv; out[2] = e2 * inv; out[3] = e3 * inv;
    }
}

// ============================================================
extern "C" void kernel_launch(void* const* d_in, const int* in_sizes, int n_in,
                              void* d_out, int out_size) {
    const float* xw   = (const float*)d_in[0];
    const int*   xi   = (const int*)d_in[1];
    const int*   tree = (const int*)d_in[2];
    const float* E    = (const float*)d_in[3];
    const float* Wz   = (const float*)d_in[4];
    const float* Uz   = (const float*)d_in[5];
    const float* bz   = (const float*)d_in[6];
    const float* Wr   = (const float*)d_in[7];
    const float* Ur   = (const float*)d_in[8];
    const float* br   = (const float*)d_in[9];
    const float* Wh   = (const float*)d_in[10];
    const float* Uh   = (const float*)d_in[11];
    const float* bh   = (const float*)d_in[12];
    const float* Wout = (const float*)d_in[13];
    const float* bout = (const float*)d_in[14];

    cudaFuncSetAttribute(levels_kernel,
                         cudaFuncAttributeMaxDynamicSharedMemorySize, NPAR * 4 + 1024);
    int perSM = 0;
    cudaOccupancyMaxActiveBlocksPerMultiprocessor(&perSM, wave_kernel, 256, 0);
    if (perSM < 1) perSM = 1;
    if (perSM > 4) perSM = 4;
    int nsm = 0;
    cudaDeviceGetAttribute(&nsm, cudaDevAttrMultiProcessorCount, 0);
    if (nsm <= 0) nsm = 148;
    int grid = perSM * nsm;
    if (grid > MAXGRID) grid = MAXGRID;

    // GEMV path only if every row fits in some block's cache
    int rpb = (NROWS + grid - 1) / grid;
    int small_thresh = (rpb <= RPB_MAX) ? 96 : 0;

    prep_kernel<<<(VOCAB * H + 255) / 256, 256>>>(E);
    xe_kernel<<<NTOT, 128>>>(xw, xi);

    dim3 gg((NPAR + BM - 1) / BM, H / BN);
    sgemm_nt<<<gg, 256>>>(Wz, bz, 0);
    sgemm_nt<<<gg, 256>>>(Wr, br, 1);
    sgemm_nt<<<gg, 256>>>(Wh, bh, 2);

    levels_kernel<<<1, 1024, NPAR * 4>>>(tree);
    wave_kernel<<<grid, 256>>>(tree, Uz, Ur, Uh, small_thresh);

    maxk_kernel<<<MAXB, 256>>>();
    final_kernel<<<1, 512>>>(Wout, bout, (float*)d_out);
    (void)in_sizes; (void)n_in; (void)out_size;
}